// round 11
// baseline (speedup 1.0000x reference)
#include <cuda_runtime.h>

// Projection: per row i of x[N,128]:
//   sq = sum(x_i^2); s = (sq-1)/(sq+1); out_i = [(1-s)*x_i, s]  -> out[N,129]
// with (1-s) = 2/(1+sq).
//
// HBM-bound streaming at ~85% of spec. R11: persistent grid-stride kernel —
// grid = 152 SMs x 6 resident CTAs; each CTA loops over row-groups. Removes
// the ~30 wave transitions (CTA launch/drain ramps) of the flat-grid
// versions, keeping loads continuously in flight. Inner body = R9 winner:
// 4 rows/warp, scalar stride-32 __ldcs loads, __stcs stores, depredicated
// tail stores.

#define D 128
#define THREADS 256
#define WARPS (THREADS / 32)
#define ROWS_PER_WARP 4
#define ROWS_PER_GROUP (WARPS * ROWS_PER_WARP)   // 32
#define GRID_BLOCKS (152 * 6)                    // persistent grid

__global__ void __launch_bounds__(THREADS) projection_kernel(
    const float* __restrict__ x, float* __restrict__ out, int n_groups)
{
    const int warp = threadIdx.x >> 5;
    const int lane = threadIdx.x & 31;

    for (long long g = blockIdx.x; g < n_groups; g += gridDim.x) {
        const long long row0 = g * ROWS_PER_GROUP + (long long)warp * ROWS_PER_WARP;
        const float* __restrict__ xr = x + row0 * D + lane;

        // Front-batched, fully coalesced streaming loads: 16 x LDG.32.CS
        float v[ROWS_PER_WARP][4];
        #pragma unroll
        for (int r = 0; r < ROWS_PER_WARP; r++)
            #pragma unroll
            for (int c = 0; c < 4; c++)
                v[r][c] = __ldcs(xr + r * D + c * 32);

        float sq[ROWS_PER_WARP];
        #pragma unroll
        for (int r = 0; r < ROWS_PER_WARP; r++)
            sq[r] = v[r][0] * v[r][0] + v[r][1] * v[r][1]
                  + v[r][2] * v[r][2] + v[r][3] * v[r][3];

        // Interleaved warp reductions; afterwards every lane holds all sq[r]
        #pragma unroll
        for (int off = 16; off > 0; off >>= 1)
            #pragma unroll
            for (int r = 0; r < ROWS_PER_WARP; r++)
                sq[r] += __shfl_xor_sync(0xFFFFFFFFu, sq[r], off);

        #pragma unroll
        for (int r = 0; r < ROWS_PER_WARP; r++) {
            const float inv   = 1.0f / (1.0f + sq[r]);
            const float scale = 2.0f * inv;        // = 1 - s

            float* __restrict__ orow = out + (row0 + r) * (D + 1);
            #pragma unroll
            for (int c = 0; c < 4; c++)
                __stcs(orow + lane + c * 32, scale * v[r][c]);
        }

        // Tail scalars: lane r stores s for row (row0 + r) — one STG, 4 lanes.
        if (lane < ROWS_PER_WARP) {
            const float sql = sq[lane];
            __stcs(out + (row0 + lane) * (D + 1) + D,
                   (sql - 1.0f) / (1.0f + sql));
        }
    }
}

extern "C" void kernel_launch(void* const* d_in, const int* in_sizes, int n_in,
                              void* d_out, int out_size)
{
    const float* x = (const float*)d_in[0];
    float* out = (float*)d_out;
    const int n_rows = in_sizes[0] / D;                     // 1048576
    const int n_groups = n_rows / ROWS_PER_GROUP;           // exact: 32768
    projection_kernel<<<GRID_BLOCKS, THREADS>>>(x, out, n_groups);
}

// round 12
// speedup vs baseline: 1.2054x; 1.2054x over previous
#include <cuda_runtime.h>

// Projection: per row i of x[N,128]:
//   sq = sum(x_i^2); s = (sq-1)/(sq+1); out_i = [(1-s)*x_i, s]  -> out[N,129]
// with (1-s) = 2/(1+sq).
//
// FINAL converged config — flat grid, HBM-bound at ~6.75TB/s (85% of spec,
// the practical ceiling for a 50/50 r/w stream with 516B-stride write rows).
// Measured evidence:
//  R1: misaligned row stores merge fully in L2 (DRAM traffic == payload)
//  R2: smem-staged aligned stores: -18% (staging cost, no traffic benefit)
//  R3: MLP 4->16 front-batched loads: +7% DRAM  (winner)
//  R4/R10: 8 rows/warp: neutral either store policy
//  R5: float4 loads: slightly worse queueing than 4x scalar LDG.32
//  R9: __stcs evict-first stores: +1.6% DRAM    (winner)
//  R11: persistent grid: -17% (loop serializes per-warp MLP; flat grid's
//       continuous CTA replacement IS the latency hiding)

#define D 128
#define THREADS 256
#define WARPS (THREADS / 32)
#define ROWS_PER_WARP 4
#define ROWS_PER_BLOCK (WARPS * ROWS_PER_WARP)   // 32

__global__ void __launch_bounds__(THREADS) projection_kernel(
    const float* __restrict__ x, float* __restrict__ out)
{
    const int warp = threadIdx.x >> 5;
    const int lane = threadIdx.x & 31;
    const long long row0 = (long long)blockIdx.x * ROWS_PER_BLOCK
                         + (long long)warp * ROWS_PER_WARP;

    const float* __restrict__ xr = x + row0 * D + lane;

    // Front-batched, fully coalesced streaming loads: 16 x LDG.32.CS
    float v[ROWS_PER_WARP][4];
    #pragma unroll
    for (int r = 0; r < ROWS_PER_WARP; r++)
        #pragma unroll
        for (int c = 0; c < 4; c++)
            v[r][c] = __ldcs(xr + r * D + c * 32);

    float sq[ROWS_PER_WARP];
    #pragma unroll
    for (int r = 0; r < ROWS_PER_WARP; r++)
        sq[r] = v[r][0] * v[r][0] + v[r][1] * v[r][1]
              + v[r][2] * v[r][2] + v[r][3] * v[r][3];

    // Interleaved warp reductions; afterwards every lane holds all sq[r]
    #pragma unroll
    for (int off = 16; off > 0; off >>= 1)
        #pragma unroll
        for (int r = 0; r < ROWS_PER_WARP; r++)
            sq[r] += __shfl_xor_sync(0xFFFFFFFFu, sq[r], off);

    // Tail scalars first (ready right after the reduction):
    // lane r stores s for row (row0 + r) — one STG, 4 active lanes.
    if (lane < ROWS_PER_WARP) {
        const float sql = sq[lane];
        __stcs(out + (row0 + lane) * (D + 1) + D, (sql - 1.0f) / (1.0f + sql));
    }

    #pragma unroll
    for (int r = 0; r < ROWS_PER_WARP; r++) {
        const float inv   = 1.0f / (1.0f + sq[r]);
        const float scale = 2.0f * inv;        // = 1 - s

        float* __restrict__ orow = out + (row0 + r) * (D + 1);
        #pragma unroll
        for (int c = 0; c < 4; c++)
            __stcs(orow + lane + c * 32, scale * v[r][c]);
    }
}

extern "C" void kernel_launch(void* const* d_in, const int* in_sizes, int n_in,
                              void* d_out, int out_size)
{
    const float* x = (const float*)d_in[0];
    float* out = (float*)d_out;
    const int n_rows = in_sizes[0] / D;                    // 1048576
    const int blocks = n_rows / ROWS_PER_BLOCK;            // exact: 32768
    projection_kernel<<<blocks, THREADS>>>(x, out);
}